// round 10
// baseline (speedup 1.0000x reference)
#include <cuda_runtime.h>
#include <math.h>
#include <stdint.h>

// Problem dims (fixed)
#define B_  64
#define T_  512
#define D_  256
#define H_  256
#define G4  1024          // 4*H
#define NBG 16            // batch groups (4 batches each)
#define NSL 8             // hidden-slice blocks per group (32 units each)
#define NB_SCAN (NBG*NSL) // 128 blocks
#define FPAD 32           // flag padding (ints) -> 128B per flag line

typedef unsigned long long u64;

// ---------------- device scratch ----------------
__device__ float g_Wc[G4 * D_];                 // combined weight W_ih @ W_att
__device__ float g_bc[G4];                      // combined bias
__device__ float g_vlin0[B_ * D_];              // vlin[:,0]
__device__ float g_a[B_ * T_];                  // attention scalars a[b,t]
__device__ float g_alpha[(size_t)T_ * B_ * H_]; // alpha[t][b][j]
__device__ float g_gates[(size_t)T_ * B_ * G4]; // input gates [t][b][grow]
__device__ float g_h[2 * NBG * NSL * 128];      // h fragments [parity][g][s][jl][b]
__device__ int   g_flags[NB_SCAN * FPAD];       // per-block publish counters (padded)

// ---------------- helpers ----------------
__device__ __forceinline__ float sigm(float x) {
    return __fdividef(1.0f, 1.0f + __expf(-x));
}
__device__ __forceinline__ float tanh_fast(float x) {
    // tanh(x) = 2*sigmoid(2x) - 1  (|rel err| ~1e-6, far under tolerance)
    return fmaf(2.0f, __fdividef(1.0f, 1.0f + __expf(-2.0f * x)), -1.0f);
}
__device__ __forceinline__ void st_release(int* p, int v) {
    asm volatile("st.global.release.gpu.b32 [%0], %1;" :: "l"(p), "r"(v) : "memory");
}
__device__ __forceinline__ int ld_acquire(const int* p) {
    int v;
    asm volatile("ld.global.acquire.gpu.b32 %0, [%1];" : "=r"(v) : "l"(p) : "memory");
    return v;
}
__device__ __forceinline__ u64 pack2(float x, float y) {
    u64 r;
    asm("mov.b64 %0, {%1, %2};" : "=l"(r) : "f"(x), "f"(y));
    return r;
}
__device__ __forceinline__ u64 fma2(u64 a, u64 b, u64 c) {
    u64 d;
    asm("fma.rn.f32x2 %0, %1, %2, %3;" : "=l"(d) : "l"(a), "l"(b), "l"(c));
    return d;
}
__device__ __forceinline__ float2 unpack2(u64 v) {
    float2 f;
    asm("mov.b64 {%0, %1}, %2;" : "=f"(f.x), "=f"(f.y) : "l"(v));
    return f;
}

// ---------------- kernel: reset barrier flags ----------------
__global__ void k_reset() {
    if (threadIdx.x < NB_SCAN) g_flags[threadIdx.x * FPAD] = 0;
}

// ---------------- kernel: Wc = W_ih @ W_att ----------------
__global__ void k_wc(const float* __restrict__ W_ih, const float* __restrict__ W_att) {
    int g = blockIdx.x;
    int k = threadIdx.x;
    __shared__ float wrow[D_];
    wrow[threadIdx.x] = W_ih[g * D_ + threadIdx.x];
    __syncthreads();
    float acc = 0.f;
#pragma unroll 8
    for (int d = 0; d < D_; d++) acc += wrow[d] * W_att[d * D_ + k];
    g_Wc[g * D_ + k] = acc;
}

// ---------------- kernel: bc = W_ih @ b_att + b_ih + b_hh ----------------
__global__ void k_bc(const float* __restrict__ W_ih, const float* __restrict__ b_att,
                     const float* __restrict__ b_ih, const float* __restrict__ b_hh) {
    __shared__ float ba[D_];
    if (threadIdx.x < D_) ba[threadIdx.x] = b_att[threadIdx.x];
    __syncthreads();
    int g = blockIdx.x * blockDim.x + threadIdx.x;
    if (g >= G4) return;
    float acc = b_ih[g] + b_hh[g];
#pragma unroll 8
    for (int d = 0; d < D_; d++) acc += W_ih[g * D_ + d] * ba[d];
    g_bc[g] = acc;
}

// ---------------- kernel: vlin0[b,:] = values[b,0,:] @ W_att^T + b_att ----------------
__global__ void k_vlin0(const float* __restrict__ values, const float* __restrict__ W_att,
                        const float* __restrict__ b_att) {
    int b = blockIdx.x;
    int d = threadIdx.x;
    __shared__ float v[D_];
    v[threadIdx.x] = values[(size_t)b * T_ * D_ + threadIdx.x];
    __syncthreads();
    float acc = b_att[d];
#pragma unroll 8
    for (int k = 0; k < D_; k++) acc += v[k] * W_att[d * D_ + k];
    g_vlin0[b * D_ + d] = acc;
}

// ---------------- kernel: a[b,t] = sigmoid(vlin0[b] . values[b,t]) ----------------
__global__ void k_a(const float* __restrict__ values) {
    int w = (blockIdx.x * blockDim.x + threadIdx.x) >> 5;
    int lane = threadIdx.x & 31;
    int b = w >> 9, t = w & (T_ - 1);
    const float* vp = values + ((size_t)b * T_ + t) * D_;
    const float* lp = g_vlin0 + b * D_;
    float acc = 0.f;
#pragma unroll
    for (int k = lane; k < D_; k += 32) acc += vp[k] * lp[k];
#pragma unroll
    for (int off = 16; off; off >>= 1) acc += __shfl_down_sync(0xffffffffu, acc, off);
    if (lane == 0) g_a[w] = 1.0f / (1.0f + expf(-acc));
}

// ---------------- kernel: alpha[t][b][d] = a[b,t] / log(e + cumsum(Deltas)[b,t,d]) ----
__global__ void k_alpha(const float* __restrict__ Deltas) {
    int b = blockIdx.x;
    int d = threadIdx.x;
    const float* dp = Deltas + (size_t)b * T_ * D_ + d;
    float acc = 0.f;
    for (int t = 0; t < T_; t++) {
        acc += dp[(size_t)t * D_];
        float av = g_a[b * T_ + t];
        g_alpha[((size_t)t * B_ + b) * H_ + d] = av / logf(2.718281828459045f + acc);
    }
}

// ---------------- big GEMM: gates[t][b][g] = values[b,t,:].Wc[g,:] + bc[g] ----------
// Tile: (64 batch x 2 t) rows x 128 n per block, 256 threads, 8x8 microtile (FFMA2).
#define PA 132   // smem row pitch (floats), float4-aligned
__global__ __launch_bounds__(256) void k_gemm(const float* __restrict__ values) {
    int t0 = blockIdx.x * 2;
    int n0 = blockIdx.y * 128;

    __shared__ float As[16 * PA];   // [k][r]  r = tt*64 + b
    __shared__ float Bs[16 * PA];   // [k][n]

    int tid = threadIdx.x;
    int tx = tid & 15;              // row quad group
    int ty = tid >> 4;              // n quad group

    const float* gp;
    float* scol;
    {
        int r = tid & 127;
        if (tid < 128) {
            int b = r & 63, tt = r >> 6;
            gp = values + ((size_t)b * T_ + t0 + tt) * D_;
            scol = As + r;
        } else {
            gp = g_Wc + (size_t)(n0 + r) * D_;
            scol = Bs + r;
        }
    }

    float4 pf0 = ((const float4*)gp)[0];
    float4 pf1 = ((const float4*)gp)[1];
    float4 pf2 = ((const float4*)gp)[2];
    float4 pf3 = ((const float4*)gp)[3];

    u64 acc[2][4][4];
#pragma unroll
    for (int a = 0; a < 2; a++)
#pragma unroll
        for (int i = 0; i < 4; i++)
#pragma unroll
            for (int j = 0; j < 4; j++) acc[a][i][j] = 0ull;

    for (int c = 0; c < 16; c++) {
        __syncthreads();
        scol[ 0 * PA] = pf0.x; scol[ 1 * PA] = pf0.y; scol[ 2 * PA] = pf0.z; scol[ 3 * PA] = pf0.w;
        scol[ 4 * PA] = pf1.x; scol[ 5 * PA] = pf1.y; scol[ 6 * PA] = pf1.z; scol[ 7 * PA] = pf1.w;
        scol[ 8 * PA] = pf2.x; scol[ 9 * PA] = pf2.y; scol[10 * PA] = pf2.z; scol[11 * PA] = pf2.w;
        scol[12 * PA] = pf3.x; scol[13 * PA] = pf3.y; scol[14 * PA] = pf3.z; scol[15 * PA] = pf3.w;
        __syncthreads();

        if (c < 15) {
            const float* np = gp + (c + 1) * 16;
            pf0 = ((const float4*)np)[0];
            pf1 = ((const float4*)np)[1];
            pf2 = ((const float4*)np)[2];
            pf3 = ((const float4*)np)[3];
        }

#pragma unroll
        for (int k = 0; k < 16; k++) {
            float4 a0 = *(const float4*)&As[k * PA + 4 * tx];
            float4 a1 = *(const float4*)&As[k * PA + 64 + 4 * tx];
            const float* bp = &Bs[k * PA + 4 * ty];
            u64 b00 = *(const u64*)(bp);
            u64 b01 = *(const u64*)(bp + 2);
            u64 b10 = *(const u64*)(bp + 64);
            u64 b11 = *(const u64*)(bp + 66);

            u64 p;
            p = pack2(a0.x, a0.x);
            acc[0][0][0] = fma2(p, b00, acc[0][0][0]); acc[0][0][1] = fma2(p, b01, acc[0][0][1]);
            acc[0][0][2] = fma2(p, b10, acc[0][0][2]); acc[0][0][3] = fma2(p, b11, acc[0][0][3]);
            p = pack2(a0.y, a0.y);
            acc[0][1][0] = fma2(p, b00, acc[0][1][0]); acc[0][1][1] = fma2(p, b01, acc[0][1][1]);
            acc[0][1][2] = fma2(p, b10, acc[0][1][2]); acc[0][1][3] = fma2(p, b11, acc[0][1][3]);
            p = pack2(a0.z, a0.z);
            acc[0][2][0] = fma2(p, b00, acc[0][2][0]); acc[0][2][1] = fma2(p, b01, acc[0][2][1]);
            acc[0][2][2] = fma2(p, b10, acc[0][2][2]); acc[0][2][3] = fma2(p, b11, acc[0][2][3]);
            p = pack2(a0.w, a0.w);
            acc[0][3][0] = fma2(p, b00, acc[0][3][0]); acc[0][3][1] = fma2(p, b01, acc[0][3][1]);
            acc[0][3][2] = fma2(p, b10, acc[0][3][2]); acc[0][3][3] = fma2(p, b11, acc[0][3][3]);
            p = pack2(a1.x, a1.x);
            acc[1][0][0] = fma2(p, b00, acc[1][0][0]); acc[1][0][1] = fma2(p, b01, acc[1][0][1]);
            acc[1][0][2] = fma2(p, b10, acc[1][0][2]); acc[1][0][3] = fma2(p, b11, acc[1][0][3]);
            p = pack2(a1.y, a1.y);
            acc[1][1][0] = fma2(p, b00, acc[1][1][0]); acc[1][1][1] = fma2(p, b01, acc[1][1][1]);
            acc[1][1][2] = fma2(p, b10, acc[1][1][2]); acc[1][1][3] = fma2(p, b11, acc[1][1][3]);
            p = pack2(a1.z, a1.z);
            acc[1][2][0] = fma2(p, b00, acc[1][2][0]); acc[1][2][1] = fma2(p, b01, acc[1][2][1]);
            acc[1][2][2] = fma2(p, b10, acc[1][2][2]); acc[1][2][3] = fma2(p, b11, acc[1][2][3]);
            p = pack2(a1.w, a1.w);
            acc[1][3][0] = fma2(p, b00, acc[1][3][0]); acc[1][3][1] = fma2(p, b01, acc[1][3][1]);
            acc[1][3][2] = fma2(p, b10, acc[1][3][2]); acc[1][3][3] = fma2(p, b11, acc[1][3][3]);
        }
    }

    float4 biasA = *(const float4*)&g_bc[n0 + 4 * ty];
    float4 biasB = *(const float4*)&g_bc[n0 + 64 + 4 * ty];
#pragma unroll
    for (int tt = 0; tt < 2; tt++) {
#pragma unroll
        for (int i = 0; i < 4; i++) {
            int b = 4 * tx + i;
            float* op = g_gates + ((size_t)(t0 + tt) * B_ + b) * G4 + n0;
            float2 p0 = unpack2(acc[tt][i][0]);
            float2 p1 = unpack2(acc[tt][i][1]);
            float2 p2 = unpack2(acc[tt][i][2]);
            float2 p3 = unpack2(acc[tt][i][3]);
            *(float4*)&op[4 * ty] =
                make_float4(p0.x + biasA.x, p0.y + biasA.y, p1.x + biasA.z, p1.y + biasA.w);
            *(float4*)&op[64 + 4 * ty] =
                make_float4(p2.x + biasB.x, p2.y + biasB.y, p3.x + biasB.z, p3.y + biasB.w);
        }
    }
}

// ---------------- persistent scan kernel ----------------
// 128 blocks = 16 groups x 8 slices. Block (g,s): batches 4g..4g+3, units 32s..32s+31.
// W_hh slice in REGISTERS (64 u64 row-pairs/thread). h exchanged through L2 (512B
// fragments); per-warp padded flags: warp ks waits only on peer ks and starts its
// k-chunk as soon as that peer publishes (communication pipelines with compute).
// NO per-step fences: st.release/ld.acquire + __syncthreads provide ordering.
__global__ __launch_bounds__(256, 1) void k_scan(const float* __restrict__ Whh,
                                                 float* __restrict__ out) {
    __shared__ float h_s2[NSL * 256];          // [ks][b][kk*2 + dup]  8KB
    __shared__ u64  psumU[32 * 65];            // [rq][(rp*8+ks)*4 + b]  pitch 65

    int tid = threadIdx.x;
    int bid = blockIdx.x;
    int g = bid >> 3, s = bid & 7;

    int ks = tid >> 5;            // warp id == peer slice polled
    int rq = tid & 31;            // row quad (rows 4rq..4rq+3)

    // ---- load W slice into registers, pre-packed as row-pairs ----
    u64 wA[32], wB[32];
    {
        int r0 = 4 * rq;
        int q = r0 >> 5;
        int jb = r0 & 31;
        const float* wb = Whh + (size_t)(q * 256 + s * 32 + jb) * 256 + 32 * ks;
#pragma unroll
        for (int kc = 0; kc < 32; kc++) {
            wA[kc] = pack2(wb[kc], wb[256 + kc]);
            wB[kc] = pack2(wb[512 + kc], wb[768 + kc]);
        }
    }

    // update identity (tid < 128)
    int ub = tid >> 5;            // 0..3 batch-local
    int jl = tid & 31;
    int bg = g * 4 + ub;          // global batch
    int jglob = s * 32 + jl;      // global hidden unit

    float c_reg = 0.f, c0_reg = 0.f;

    // ---- prologue t = 0 (h=0, c=0; carry c stays zero — faithful quirk) ----
    if (tid < 128) {
        const float* g0 = g_gates + (size_t)bg * G4;
        float zi = g0[0 * H_ + jglob];
        float zg = g0[2 * H_ + jglob];
        float zo = g0[3 * H_ + jglob];
        c0_reg = sigm(zi) * tanh_fast(zg);
        float h1 = sigm(zo) * tanh_fast(c0_reg);
        g_h[((0 * NBG + g) * NSL + s) * 128 + jl * 4 + ub] = h1;   // parity 0
        out[(size_t)bg * (T_ * H_) + jglob] = h1;
    }
    __syncthreads();
    if (tid == 0) st_release(&g_flags[bid * FPAD], 1);

    for (int t = 1; t < T_; t++) {
        // prefetch input gates + alpha (independent of flags, hides DRAM latency)
        float gin0 = 0.f, gin1 = 0.f, gin2 = 0.f, gin3 = 0.f, al = 0.f;
        if (tid < 128) {
            const float* gt = g_gates + ((size_t)t * B_ + bg) * G4;
            gin0 = gt[0 * H_ + jglob];
            gin1 = gt[1 * H_ + jglob];
            gin2 = gt[2 * H_ + jglob];
            gin3 = gt[3 * H_ + jglob];
            al   = g_alpha[((size_t)t * B_ + bg) * H_ + jglob];
        }

        // per-warp wait: only on the peer producing my k-chunk (padded flag line)
        {
            const int* fp = &g_flags[(g * 8 + ks) * FPAD];
            while (ld_acquire(fp) < t) { }
        }
        // fetch peer fragment [jl][b] (coalesced float4) and stage duplicated pairs
        {
            int par = (t - 1) & 1;
            float4 hv = *(const float4*)(g_h + ((size_t)(par * NBG + g) * NSL + ks) * 128 + rq * 4);
            float2* d = (float2*)(h_s2 + ks * 256);
            d[0 * 32 + rq] = make_float2(hv.x, hv.x);
            d[1 * 32 + rq] = make_float2(hv.y, hv.y);
            d[2 * 32 + rq] = make_float2(hv.z, hv.z);
            d[3 * 32 + rq] = make_float2(hv.w, hv.w);
        }
        __syncwarp();

        // dot: W in regs, h via broadcast LDS.64, pure FFMA2
        {
            const float* hp = h_s2 + ks * 256;
            u64 a00 = 0, a01 = 0, a02 = 0, a03 = 0;
            u64 a10 = 0, a11 = 0, a12 = 0, a13 = 0;
#pragma unroll
            for (int kc = 0; kc < 32; kc++) {
                u64 h0 = *(const u64*)(hp + 2 * kc);
                u64 h1 = *(const u64*)(hp + 64 + 2 * kc);
                u64 h2 = *(const u64*)(hp + 128 + 2 * kc);
                u64 h3 = *(const u64*)(hp + 192 + 2 * kc);
                a00 = fma2(wA[kc], h0, a00);
                a01 = fma2(wA[kc], h1, a01);
                a02 = fma2(wA[kc], h2, a02);
                a03 = fma2(wA[kc], h3, a03);
                a10 = fma2(wB[kc], h0, a10);
                a11 = fma2(wB[kc], h1, a11);
                a12 = fma2(wB[kc], h2, a12);
                a13 = fma2(wB[kc], h3, a13);
            }
            u64* pb = psumU + rq * 65 + ks * 4;
            pb[0] = a00; pb[1] = a01; pb[2] = a02; pb[3] = a03;
            pb[32 + 0] = a10; pb[32 + 1] = a11; pb[32 + 2] = a12; pb[32 + 3] = a13;
        }
        __syncthreads();   // psum ready

        // cell update: 128 threads, one per (batch, unit)
        if (tid < 128) {
            const float* pf = (const float*)psumU;
            int rqo = (jl >> 2);
            int off = ((jl >> 1) & 1) * 64 + ub * 2 + (jl & 1);
            float z[4] = {gin0, gin1, gin2, gin3};
#pragma unroll
            for (int q = 0; q < 4; q++) {
                const float* row = pf + (size_t)(q * 8 + rqo) * 130 + off;
                float sum = 0.f;
#pragma unroll
                for (int k8 = 0; k8 < 8; k8++) sum += row[k8 * 8];
                z[q] += sum;
            }
            float c = al * c0_reg + (1.f - al) * c_reg;
            c = sigm(z[1]) * c + sigm(z[0]) * tanh_fast(z[2]);
            c_reg = c;
            float h = sigm(z[3]) * tanh_fast(c);
            if (t < T_ - 1)
                g_h[((size_t)((t & 1) * NBG + g) * NSL + s) * 128 + jl * 4 + ub] = h;
            out[(size_t)bg * (T_ * H_) + (size_t)t * H_ + jglob] = h;
        }
        __syncthreads();   // all warps done reading h(t-1) / psum; h(t) stores issued
        if (t < T_ - 1) {
            if (tid == 0) st_release(&g_flags[bid * FPAD], t + 1);
        }
    }
}

// ---------------- launch ----------------
extern "C" void kernel_launch(void* const* d_in, const int* in_sizes, int n_in,
                              void* d_out, int out_size) {
    (void)in_sizes; (void)n_in; (void)out_size;
    const float* values = (const float*)d_in[0];
    const float* Deltas = (const float*)d_in[1];
    const float* W_att  = (const float*)d_in[2];
    const float* b_att  = (const float*)d_in[3];
    const float* W_ih   = (const float*)d_in[4];
    const float* W_hh   = (const float*)d_in[5];
    const float* b_ih   = (const float*)d_in[6];
    const float* b_hh   = (const float*)d_in[7];
    float* out = (float*)d_out;

    k_wc<<<G4, D_>>>(W_ih, W_att);
    k_bc<<<G4 / 256, 256>>>(W_ih, b_att, b_ih, b_hh);
    k_vlin0<<<B_, D_>>>(values, W_att, b_att);
    k_gemm<<<dim3(T_ / 2, G4 / 128), 256>>>(values);
    k_a<<<(B_ * T_ * 32) / 256, 256>>>(values);
    k_alpha<<<B_, D_>>>(Deltas);
    k_reset<<<1, NB_SCAN>>>();
    k_scan<<<NB_SCAN, 256>>>(W_hh, out);
}

// round 11
// speedup vs baseline: 1.0063x; 1.0063x over previous
#include <cuda_runtime.h>
#include <math.h>
#include <stdint.h>

// Problem dims (fixed)
#define B_  64
#define T_  512
#define D_  256
#define H_  256
#define G4  1024          // 4*H
#define NBG 16            // batch groups (4 batches each)
#define NSL 8             // hidden-slice blocks per group (32 units each)
#define NB_SCAN (NBG*NSL) // 128 blocks
#define FPAD 32           // flag padding (ints) -> 128B per flag line

typedef unsigned long long u64;

// ---------------- device scratch ----------------
__device__ float g_Wc[G4 * D_];                 // combined weight W_ih @ W_att
__device__ float g_bc[G4];                      // combined bias
__device__ float g_vlin0[B_ * D_];              // vlin[:,0]
__device__ float g_a[B_ * T_];                  // attention scalars a[b,t]
__device__ float g_alpha[(size_t)T_ * B_ * H_]; // alpha[t][b][j]
__device__ float g_gates[(size_t)T_ * B_ * G4]; // input gates [t][b][grow]
__device__ float g_h[2 * NBG * NSL * 128];      // h fragments [parity][g][s][jl][b]
__device__ int   g_flags[NB_SCAN * FPAD];       // per-block publish counters (padded)

// ---------------- helpers ----------------
__device__ __forceinline__ float sigm(float x) {
    return __fdividef(1.0f, 1.0f + __expf(-x));
}
__device__ __forceinline__ float tanh_fast(float x) {
    // tanh(x) = 2*sigmoid(2x) - 1  (|rel err| ~1e-6, far under tolerance)
    return fmaf(2.0f, __fdividef(1.0f, 1.0f + __expf(-2.0f * x)), -1.0f);
}
__device__ __forceinline__ void st_release(int* p, int v) {
    asm volatile("st.global.release.gpu.b32 [%0], %1;" :: "l"(p), "r"(v) : "memory");
}
__device__ __forceinline__ int ld_acquire(const int* p) {
    int v;
    asm volatile("ld.global.acquire.gpu.b32 %0, [%1];" : "=r"(v) : "l"(p) : "memory");
    return v;
}
__device__ __forceinline__ u64 pack2(float x, float y) {
    u64 r;
    asm("mov.b64 %0, {%1, %2};" : "=l"(r) : "f"(x), "f"(y));
    return r;
}
__device__ __forceinline__ u64 fma2(u64 a, u64 b, u64 c) {
    u64 d;
    asm("fma.rn.f32x2 %0, %1, %2, %3;" : "=l"(d) : "l"(a), "l"(b), "l"(c));
    return d;
}
__device__ __forceinline__ float2 unpack2(u64 v) {
    float2 f;
    asm("mov.b64 {%0, %1}, %2;" : "=f"(f.x), "=f"(f.y) : "l"(v));
    return f;
}

// ---------------- kernel: reset barrier flags ----------------
__global__ void k_reset() {
    if (threadIdx.x < NB_SCAN) g_flags[threadIdx.x * FPAD] = 0;
}

// ---------------- kernel: Wc = W_ih @ W_att ----------------
__global__ void k_wc(const float* __restrict__ W_ih, const float* __restrict__ W_att) {
    int g = blockIdx.x;
    int k = threadIdx.x;
    __shared__ float wrow[D_];
    wrow[threadIdx.x] = W_ih[g * D_ + threadIdx.x];
    __syncthreads();
    float acc = 0.f;
#pragma unroll 8
    for (int d = 0; d < D_; d++) acc += wrow[d] * W_att[d * D_ + k];
    g_Wc[g * D_ + k] = acc;
}

// ---------------- kernel: bc = W_ih @ b_att + b_ih + b_hh ----------------
__global__ void k_bc(const float* __restrict__ W_ih, const float* __restrict__ b_att,
                     const float* __restrict__ b_ih, const float* __restrict__ b_hh) {
    __shared__ float ba[D_];
    if (threadIdx.x < D_) ba[threadIdx.x] = b_att[threadIdx.x];
    __syncthreads();
    int g = blockIdx.x * blockDim.x + threadIdx.x;
    if (g >= G4) return;
    float acc = b_ih[g] + b_hh[g];
#pragma unroll 8
    for (int d = 0; d < D_; d++) acc += W_ih[g * D_ + d] * ba[d];
    g_bc[g] = acc;
}

// ---------------- kernel: vlin0[b,:] = values[b,0,:] @ W_att^T + b_att ----------------
__global__ void k_vlin0(const float* __restrict__ values, const float* __restrict__ W_att,
                        const float* __restrict__ b_att) {
    int b = blockIdx.x;
    int d = threadIdx.x;
    __shared__ float v[D_];
    v[threadIdx.x] = values[(size_t)b * T_ * D_ + threadIdx.x];
    __syncthreads();
    float acc = b_att[d];
#pragma unroll 8
    for (int k = 0; k < D_; k++) acc += v[k] * W_att[d * D_ + k];
    g_vlin0[b * D_ + d] = acc;
}

// ---------------- kernel: a[b,t] = sigmoid(vlin0[b] . values[b,t]) ----------------
__global__ void k_a(const float* __restrict__ values) {
    int w = (blockIdx.x * blockDim.x + threadIdx.x) >> 5;
    int lane = threadIdx.x & 31;
    int b = w >> 9, t = w & (T_ - 1);
    const float* vp = values + ((size_t)b * T_ + t) * D_;
    const float* lp = g_vlin0 + b * D_;
    float acc = 0.f;
#pragma unroll
    for (int k = lane; k < D_; k += 32) acc += vp[k] * lp[k];
#pragma unroll
    for (int off = 16; off; off >>= 1) acc += __shfl_down_sync(0xffffffffu, acc, off);
    if (lane == 0) g_a[w] = 1.0f / (1.0f + expf(-acc));
}

// ---------------- kernel: alpha[t][b][d] = a[b,t] / log(e + cumsum(Deltas)[b,t,d]) ----
__global__ void k_alpha(const float* __restrict__ Deltas) {
    int b = blockIdx.x;
    int d = threadIdx.x;
    const float* dp = Deltas + (size_t)b * T_ * D_ + d;
    float acc = 0.f;
    for (int t = 0; t < T_; t++) {
        acc += dp[(size_t)t * D_];
        float av = g_a[b * T_ + t];
        g_alpha[((size_t)t * B_ + b) * H_ + d] = av / logf(2.718281828459045f + acc);
    }
}

// ---------------- big GEMM: gates[t][b][g] = values[b,t,:].Wc[g,:] + bc[g] ----------
// Tile: (64 batch x 2 t) rows x 128 n per block, 256 threads, 8x8 microtile (FFMA2).
#define PA 132   // smem row pitch (floats), float4-aligned
__global__ __launch_bounds__(256) void k_gemm(const float* __restrict__ values) {
    int t0 = blockIdx.x * 2;
    int n0 = blockIdx.y * 128;

    __shared__ float As[16 * PA];   // [k][r]  r = tt*64 + b
    __shared__ float Bs[16 * PA];   // [k][n]

    int tid = threadIdx.x;
    int tx = tid & 15;              // row quad group
    int ty = tid >> 4;              // n quad group

    const float* gp;
    float* scol;
    {
        int r = tid & 127;
        if (tid < 128) {
            int b = r & 63, tt = r >> 6;
            gp = values + ((size_t)b * T_ + t0 + tt) * D_;
            scol = As + r;
        } else {
            gp = g_Wc + (size_t)(n0 + r) * D_;
            scol = Bs + r;
        }
    }

    float4 pf0 = ((const float4*)gp)[0];
    float4 pf1 = ((const float4*)gp)[1];
    float4 pf2 = ((const float4*)gp)[2];
    float4 pf3 = ((const float4*)gp)[3];

    u64 acc[2][4][4];
#pragma unroll
    for (int a = 0; a < 2; a++)
#pragma unroll
        for (int i = 0; i < 4; i++)
#pragma unroll
            for (int j = 0; j < 4; j++) acc[a][i][j] = 0ull;

    for (int c = 0; c < 16; c++) {
        __syncthreads();
        scol[ 0 * PA] = pf0.x; scol[ 1 * PA] = pf0.y; scol[ 2 * PA] = pf0.z; scol[ 3 * PA] = pf0.w;
        scol[ 4 * PA] = pf1.x; scol[ 5 * PA] = pf1.y; scol[ 6 * PA] = pf1.z; scol[ 7 * PA] = pf1.w;
        scol[ 8 * PA] = pf2.x; scol[ 9 * PA] = pf2.y; scol[10 * PA] = pf2.z; scol[11 * PA] = pf2.w;
        scol[12 * PA] = pf3.x; scol[13 * PA] = pf3.y; scol[14 * PA] = pf3.z; scol[15 * PA] = pf3.w;
        __syncthreads();

        if (c < 15) {
            const float* np = gp + (c + 1) * 16;
            pf0 = ((const float4*)np)[0];
            pf1 = ((const float4*)np)[1];
            pf2 = ((const float4*)np)[2];
            pf3 = ((const float4*)np)[3];
        }

#pragma unroll
        for (int k = 0; k < 16; k++) {
            float4 a0 = *(const float4*)&As[k * PA + 4 * tx];
            float4 a1 = *(const float4*)&As[k * PA + 64 + 4 * tx];
            const float* bp = &Bs[k * PA + 4 * ty];
            u64 b00 = *(const u64*)(bp);
            u64 b01 = *(const u64*)(bp + 2);
            u64 b10 = *(const u64*)(bp + 64);
            u64 b11 = *(const u64*)(bp + 66);

            u64 p;
            p = pack2(a0.x, a0.x);
            acc[0][0][0] = fma2(p, b00, acc[0][0][0]); acc[0][0][1] = fma2(p, b01, acc[0][0][1]);
            acc[0][0][2] = fma2(p, b10, acc[0][0][2]); acc[0][0][3] = fma2(p, b11, acc[0][0][3]);
            p = pack2(a0.y, a0.y);
            acc[0][1][0] = fma2(p, b00, acc[0][1][0]); acc[0][1][1] = fma2(p, b01, acc[0][1][1]);
            acc[0][1][2] = fma2(p, b10, acc[0][1][2]); acc[0][1][3] = fma2(p, b11, acc[0][1][3]);
            p = pack2(a0.z, a0.z);
            acc[0][2][0] = fma2(p, b00, acc[0][2][0]); acc[0][2][1] = fma2(p, b01, acc[0][2][1]);
            acc[0][2][2] = fma2(p, b10, acc[0][2][2]); acc[0][2][3] = fma2(p, b11, acc[0][2][3]);
            p = pack2(a0.w, a0.w);
            acc[0][3][0] = fma2(p, b00, acc[0][3][0]); acc[0][3][1] = fma2(p, b01, acc[0][3][1]);
            acc[0][3][2] = fma2(p, b10, acc[0][3][2]); acc[0][3][3] = fma2(p, b11, acc[0][3][3]);
            p = pack2(a1.x, a1.x);
            acc[1][0][0] = fma2(p, b00, acc[1][0][0]); acc[1][0][1] = fma2(p, b01, acc[1][0][1]);
            acc[1][0][2] = fma2(p, b10, acc[1][0][2]); acc[1][0][3] = fma2(p, b11, acc[1][0][3]);
            p = pack2(a1.y, a1.y);
            acc[1][1][0] = fma2(p, b00, acc[1][1][0]); acc[1][1][1] = fma2(p, b01, acc[1][1][1]);
            acc[1][1][2] = fma2(p, b10, acc[1][1][2]); acc[1][1][3] = fma2(p, b11, acc[1][1][3]);
            p = pack2(a1.z, a1.z);
            acc[1][2][0] = fma2(p, b00, acc[1][2][0]); acc[1][2][1] = fma2(p, b01, acc[1][2][1]);
            acc[1][2][2] = fma2(p, b10, acc[1][2][2]); acc[1][2][3] = fma2(p, b11, acc[1][2][3]);
            p = pack2(a1.w, a1.w);
            acc[1][3][0] = fma2(p, b00, acc[1][3][0]); acc[1][3][1] = fma2(p, b01, acc[1][3][1]);
            acc[1][3][2] = fma2(p, b10, acc[1][3][2]); acc[1][3][3] = fma2(p, b11, acc[1][3][3]);
        }
    }

    float4 biasA = *(const float4*)&g_bc[n0 + 4 * ty];
    float4 biasB = *(const float4*)&g_bc[n0 + 64 + 4 * ty];
#pragma unroll
    for (int tt = 0; tt < 2; tt++) {
#pragma unroll
        for (int i = 0; i < 4; i++) {
            int b = 4 * tx + i;
            float* op = g_gates + ((size_t)(t0 + tt) * B_ + b) * G4 + n0;
            float2 p0 = unpack2(acc[tt][i][0]);
            float2 p1 = unpack2(acc[tt][i][1]);
            float2 p2 = unpack2(acc[tt][i][2]);
            float2 p3 = unpack2(acc[tt][i][3]);
            *(float4*)&op[4 * ty] =
                make_float4(p0.x + biasA.x, p0.y + biasA.y, p1.x + biasA.z, p1.y + biasA.w);
            *(float4*)&op[64 + 4 * ty] =
                make_float4(p2.x + biasB.x, p2.y + biasB.y, p3.x + biasB.z, p3.y + biasB.w);
        }
    }
}

// ---------------- persistent scan kernel ----------------
// 128 blocks = 16 groups x 8 slices. Block (g,s): batches 4g..4g+3, units 32s..32s+31.
// W_hh slice in REGISTERS (64 u64 row-pairs/thread). h exchanged through L2 (512B
// fragments); per-warp padded flags: warp ks waits only on peer ks and starts its
// k-chunk as soon as that peer publishes (communication pipelines with compute).
// NO per-step fences: st.release/ld.acquire + __syncthreads provide ordering.
__global__ __launch_bounds__(256, 1) void k_scan(const float* __restrict__ Whh,
                                                 float* __restrict__ out) {
    __shared__ float h_s2[NSL * 256];          // [ks][b][kk*2 + dup]  8KB
    __shared__ u64  psumU[32 * 65];            // [rq][(rp*8+ks)*4 + b]  pitch 65

    int tid = threadIdx.x;
    int bid = blockIdx.x;
    int g = bid >> 3, s = bid & 7;

    int ks = tid >> 5;            // warp id == peer slice polled
    int rq = tid & 31;            // row quad (rows 4rq..4rq+3)

    // ---- load W slice into registers, pre-packed as row-pairs ----
    u64 wA[32], wB[32];
    {
        int r0 = 4 * rq;
        int q = r0 >> 5;
        int jb = r0 & 31;
        const float* wb = Whh + (size_t)(q * 256 + s * 32 + jb) * 256 + 32 * ks;
#pragma unroll
        for (int kc = 0; kc < 32; kc++) {
            wA[kc] = pack2(wb[kc], wb[256 + kc]);
            wB[kc] = pack2(wb[512 + kc], wb[768 + kc]);
        }
    }

    // update identity (tid < 128)
    int ub = tid >> 5;            // 0..3 batch-local
    int jl = tid & 31;
    int bg = g * 4 + ub;          // global batch
    int jglob = s * 32 + jl;      // global hidden unit

    float c_reg = 0.f, c0_reg = 0.f;

    // ---- prologue t = 0 (h=0, c=0; carry c stays zero — faithful quirk) ----
    if (tid < 128) {
        const float* g0 = g_gates + (size_t)bg * G4;
        float zi = g0[0 * H_ + jglob];
        float zg = g0[2 * H_ + jglob];
        float zo = g0[3 * H_ + jglob];
        c0_reg = sigm(zi) * tanh_fast(zg);
        float h1 = sigm(zo) * tanh_fast(c0_reg);
        g_h[((0 * NBG + g) * NSL + s) * 128 + jl * 4 + ub] = h1;   // parity 0
        out[(size_t)bg * (T_ * H_) + jglob] = h1;
    }
    __syncthreads();
    if (tid == 0) st_release(&g_flags[bid * FPAD], 1);

    for (int t = 1; t < T_; t++) {
        // prefetch input gates + alpha (independent of flags, hides DRAM latency)
        float gin0 = 0.f, gin1 = 0.f, gin2 = 0.f, gin3 = 0.f, al = 0.f;
        if (tid < 128) {
            const float* gt = g_gates + ((size_t)t * B_ + bg) * G4;
            gin0 = gt[0 * H_ + jglob];
            gin1 = gt[1 * H_ + jglob];
            gin2 = gt[2 * H_ + jglob];
            gin3 = gt[3 * H_ + jglob];
            al   = g_alpha[((size_t)t * B_ + bg) * H_ + jglob];
        }

        // per-warp wait: only on the peer producing my k-chunk (padded flag line)
        {
            const int* fp = &g_flags[(g * 8 + ks) * FPAD];
            while (ld_acquire(fp) < t) { }
        }
        // fetch peer fragment [jl][b] (coalesced float4) and stage duplicated pairs
        {
            int par = (t - 1) & 1;
            float4 hv = *(const float4*)(g_h + ((size_t)(par * NBG + g) * NSL + ks) * 128 + rq * 4);
            float2* d = (float2*)(h_s2 + ks * 256);
            d[0 * 32 + rq] = make_float2(hv.x, hv.x);
            d[1 * 32 + rq] = make_float2(hv.y, hv.y);
            d[2 * 32 + rq] = make_float2(hv.z, hv.z);
            d[3 * 32 + rq] = make_float2(hv.w, hv.w);
        }
        __syncwarp();

        // dot: W in regs, h via broadcast LDS.64, pure FFMA2
        {
            const float* hp = h_s2 + ks * 256;
            u64 a00 = 0, a01 = 0, a02 = 0, a03 = 0;
            u64 a10 = 0, a11 = 0, a12 = 0, a13 = 0;
#pragma unroll
            for (int kc = 0; kc < 32; kc++) {
                u64 h0 = *(const u64*)(hp + 2 * kc);
                u64 h1 = *(const u64*)(hp + 64 + 2 * kc);
                u64 h2 = *(const u64*)(hp + 128 + 2 * kc);
                u64 h3 = *(const u64*)(hp + 192 + 2 * kc);
                a00 = fma2(wA[kc], h0, a00);
                a01 = fma2(wA[kc], h1, a01);
                a02 = fma2(wA[kc], h2, a02);
                a03 = fma2(wA[kc], h3, a03);
                a10 = fma2(wB[kc], h0, a10);
                a11 = fma2(wB[kc], h1, a11);
                a12 = fma2(wB[kc], h2, a12);
                a13 = fma2(wB[kc], h3, a13);
            }
            u64* pb = psumU + rq * 65 + ks * 4;
            pb[0] = a00; pb[1] = a01; pb[2] = a02; pb[3] = a03;
            pb[32 + 0] = a10; pb[32 + 1] = a11; pb[32 + 2] = a12; pb[32 + 3] = a13;
        }
        __syncthreads();   // psum ready

        // cell update: 128 threads, one per (batch, unit)
        if (tid < 128) {
            const float* pf = (const float*)psumU;
            int rqo = (jl >> 2);
            int off = ((jl >> 1) & 1) * 64 + ub * 2 + (jl & 1);
            float z[4] = {gin0, gin1, gin2, gin3};
#pragma unroll
            for (int q = 0; q < 4; q++) {
                const float* row = pf + (size_t)(q * 8 + rqo) * 130 + off;
                float sum = 0.f;
#pragma unroll
                for (int k8 = 0; k8 < 8; k8++) sum += row[k8 * 8];
                z[q] += sum;
            }
            float c = al * c0_reg + (1.f - al) * c_reg;
            c = sigm(z[1]) * c + sigm(z[0]) * tanh_fast(z[2]);
            c_reg = c;
            float h = sigm(z[3]) * tanh_fast(c);
            if (t < T_ - 1)
                g_h[((size_t)((t & 1) * NBG + g) * NSL + s) * 128 + jl * 4 + ub] = h;
            out[(size_t)bg * (T_ * H_) + (size_t)t * H_ + jglob] = h;
        }
        __syncthreads();   // all warps done reading h(t-1) / psum; h(t) stores issued
        if (t < T_ - 1) {
            if (tid == 0) st_release(&g_flags[bid * FPAD], t + 1);
        }
    }
}

// ---------------- launch ----------------
extern "C" void kernel_launch(void* const* d_in, const int* in_sizes, int n_in,
                              void* d_out, int out_size) {
    (void)in_sizes; (void)n_in; (void)out_size;
    const float* values = (const float*)d_in[0];
    const float* Deltas = (const float*)d_in[1];
    const float* W_att  = (const float*)d_in[2];
    const float* b_att  = (const float*)d_in[3];
    const float* W_ih   = (const float*)d_in[4];
    const float* W_hh   = (const float*)d_in[5];
    const float* b_ih   = (const float*)d_in[6];
    const float* b_hh   = (const float*)d_in[7];
    float* out = (float*)d_out;

    k_wc<<<G4, D_>>>(W_ih, W_att);
    k_bc<<<G4 / 256, 256>>>(W_ih, b_att, b_ih, b_hh);
    k_vlin0<<<B_, D_>>>(values, W_att, b_att);
    k_gemm<<<dim3(T_ / 2, G4 / 128), 256>>>(values);
    k_a<<<(B_ * T_ * 32) / 256, 256>>>(values);
    k_alpha<<<B_, D_>>>(Deltas);
    k_reset<<<1, NB_SCAN>>>();
    k_scan<<<NB_SCAN, 256>>>(W_hh, out);
}

// round 12
// speedup vs baseline: 1.3429x; 1.3345x over previous
#include <cuda_runtime.h>
#include <math.h>
#include <stdint.h>

// Problem dims (fixed)
#define B_  64
#define T_  512
#define D_  256
#define H_  256
#define G4  1024          // 4*H
#define NBG 16            // batch groups (4 batches each)
#define NSL 8             // hidden-slice blocks per group (32 units each)
#define NB_SCAN (NBG*NSL) // 128 blocks
#define SENT 0x7FBFFFFFu  // NaN sentinel (unreachable from finite sigm*tanh)

typedef unsigned long long u64;

// ---------------- device scratch ----------------
__device__ float g_Wc[G4 * D_];                 // combined weight W_ih @ W_att
__device__ float g_bc[G4];                      // combined bias
__device__ float g_vlin0[B_ * D_];              // vlin[:,0]
__device__ float g_a[B_ * T_];                  // attention scalars a[b,t]
__device__ float g_alpha[(size_t)T_ * B_ * H_]; // alpha[t][b][j]
__device__ float g_gates[(size_t)T_ * B_ * G4]; // input gates [t][b][grow]
__device__ float g_hT[(size_t)T_ * NBG * NSL * 128]; // per-step h fragments [t][g][s][jl][b]

// ---------------- helpers ----------------
__device__ __forceinline__ float sigm(float x) {
    return __fdividef(1.0f, 1.0f + __expf(-x));
}
__device__ __forceinline__ float tanh_fast(float x) {
    return fmaf(2.0f, __fdividef(1.0f, 1.0f + __expf(-2.0f * x)), -1.0f);
}
__device__ __forceinline__ u64 pack2(float x, float y) {
    u64 r;
    asm("mov.b64 %0, {%1, %2};" : "=l"(r) : "f"(x), "f"(y));
    return r;
}
__device__ __forceinline__ u64 fma2(u64 a, u64 b, u64 c) {
    u64 d;
    asm("fma.rn.f32x2 %0, %1, %2, %3;" : "=l"(d) : "l"(a), "l"(b), "l"(c));
    return d;
}
__device__ __forceinline__ float2 unpack2(u64 v) {
    float2 f;
    asm("mov.b64 {%0, %1}, %2;" : "=f"(f.x), "=f"(f.y) : "l"(v));
    return f;
}
__device__ __forceinline__ uint4 ld_vol4(const float* p) {
    uint4 v;
    asm volatile("ld.volatile.global.v4.u32 {%0,%1,%2,%3}, [%4];"
                 : "=r"(v.x), "=r"(v.y), "=r"(v.z), "=r"(v.w) : "l"(p));
    return v;
}
__device__ __forceinline__ void st_vol(float* p, float v) {
    asm volatile("st.volatile.global.f32 [%0], %1;" :: "l"(p), "f"(v) : "memory");
}

// ---------------- kernel: poison per-step h buffers with sentinel ----------------
__global__ void k_poison() {
    size_t i = (size_t)blockIdx.x * blockDim.x + threadIdx.x;
    uint4* p = (uint4*)g_hT;
    p[i] = make_uint4(SENT, SENT, SENT, SENT);
}

// ---------------- kernel: Wc = W_ih @ W_att ----------------
__global__ void k_wc(const float* __restrict__ W_ih, const float* __restrict__ W_att) {
    int g = blockIdx.x;
    int k = threadIdx.x;
    __shared__ float wrow[D_];
    wrow[threadIdx.x] = W_ih[g * D_ + threadIdx.x];
    __syncthreads();
    float acc = 0.f;
#pragma unroll 8
    for (int d = 0; d < D_; d++) acc += wrow[d] * W_att[d * D_ + k];
    g_Wc[g * D_ + k] = acc;
}

// ---------------- kernel: bc = W_ih @ b_att + b_ih + b_hh ----------------
__global__ void k_bc(const float* __restrict__ W_ih, const float* __restrict__ b_att,
                     const float* __restrict__ b_ih, const float* __restrict__ b_hh) {
    __shared__ float ba[D_];
    if (threadIdx.x < D_) ba[threadIdx.x] = b_att[threadIdx.x];
    __syncthreads();
    int g = blockIdx.x * blockDim.x + threadIdx.x;
    if (g >= G4) return;
    float acc = b_ih[g] + b_hh[g];
#pragma unroll 8
    for (int d = 0; d < D_; d++) acc += W_ih[g * D_ + d] * ba[d];
    g_bc[g] = acc;
}

// ---------------- kernel: vlin0[b,:] = values[b,0,:] @ W_att^T + b_att ----------------
__global__ void k_vlin0(const float* __restrict__ values, const float* __restrict__ W_att,
                        const float* __restrict__ b_att) {
    int b = blockIdx.x;
    int d = threadIdx.x;
    __shared__ float v[D_];
    v[threadIdx.x] = values[(size_t)b * T_ * D_ + threadIdx.x];
    __syncthreads();
    float acc = b_att[d];
#pragma unroll 8
    for (int k = 0; k < D_; k++) acc += v[k] * W_att[d * D_ + k];
    g_vlin0[b * D_ + d] = acc;
}

// ---------------- kernel: a[b,t] = sigmoid(vlin0[b] . values[b,t]) ----------------
__global__ void k_a(const float* __restrict__ values) {
    int w = (blockIdx.x * blockDim.x + threadIdx.x) >> 5;
    int lane = threadIdx.x & 31;
    int b = w >> 9, t = w & (T_ - 1);
    const float* vp = values + ((size_t)b * T_ + t) * D_;
    const float* lp = g_vlin0 + b * D_;
    float acc = 0.f;
#pragma unroll
    for (int k = lane; k < D_; k += 32) acc += vp[k] * lp[k];
#pragma unroll
    for (int off = 16; off; off >>= 1) acc += __shfl_down_sync(0xffffffffu, acc, off);
    if (lane == 0) g_a[w] = 1.0f / (1.0f + expf(-acc));
}

// ---------------- kernel: alpha[t][b][d] = a[b,t] / log(e + cumsum(Deltas)[b,t,d]) ----
__global__ void k_alpha(const float* __restrict__ Deltas) {
    int b = blockIdx.x;
    int d = threadIdx.x;
    const float* dp = Deltas + (size_t)b * T_ * D_ + d;
    const float* ap = g_a + b * T_;
    float acc = 0.f;
    for (int t = 0; t < T_; t += 4) {
        float d0 = dp[(size_t)(t + 0) * D_];
        float d1 = dp[(size_t)(t + 1) * D_];
        float d2 = dp[(size_t)(t + 2) * D_];
        float d3 = dp[(size_t)(t + 3) * D_];
        float a0v = ap[t + 0], a1v = ap[t + 1], a2v = ap[t + 2], a3v = ap[t + 3];
        float c0 = acc + d0;
        float c1 = c0 + d1;
        float c2 = c1 + d2;
        float c3 = c2 + d3;
        acc = c3;
        float* op = g_alpha + ((size_t)t * B_ + b) * H_ + d;
        op[0 * B_ * H_] = __fdividef(a0v, __logf(2.718281828459045f + c0));
        op[1 * B_ * H_] = __fdividef(a1v, __logf(2.718281828459045f + c1));
        op[2 * B_ * H_] = __fdividef(a2v, __logf(2.718281828459045f + c2));
        op[3 * B_ * H_] = __fdividef(a3v, __logf(2.718281828459045f + c3));
    }
}

// ---------------- big GEMM: gates[t][b][g] = values[b,t,:].Wc[g,:] + bc[g] ----------
// Tile: (64 batch x 2 t) rows x 128 n per block, 256 threads, 8x8 microtile (FFMA2).
// B operand read as LDS.128 (reinterpreted to u64 pairs) -> crossbar below FMA floor.
#define PA 132   // smem row pitch (floats), float4-aligned
__global__ __launch_bounds__(256) void k_gemm(const float* __restrict__ values) {
    int t0 = blockIdx.x * 2;
    int n0 = blockIdx.y * 128;

    __shared__ float As[16 * PA];   // [k][r]  r = tt*64 + b
    __shared__ float Bs[16 * PA];   // [k][n]

    int tid = threadIdx.x;
    int tx = tid & 15;              // row quad group
    int ty = tid >> 4;              // n quad group

    const float* gp;
    float* scol;
    {
        int r = tid & 127;
        if (tid < 128) {
            int b = r & 63, tt = r >> 6;
            gp = values + ((size_t)b * T_ + t0 + tt) * D_;
            scol = As + r;
        } else {
            gp = g_Wc + (size_t)(n0 + r) * D_;
            scol = Bs + r;
        }
    }

    float4 pf0 = ((const float4*)gp)[0];
    float4 pf1 = ((const float4*)gp)[1];
    float4 pf2 = ((const float4*)gp)[2];
    float4 pf3 = ((const float4*)gp)[3];

    u64 acc[2][4][4];
#pragma unroll
    for (int a = 0; a < 2; a++)
#pragma unroll
        for (int i = 0; i < 4; i++)
#pragma unroll
            for (int j = 0; j < 4; j++) acc[a][i][j] = 0ull;

    for (int c = 0; c < 16; c++) {
        __syncthreads();
        scol[ 0 * PA] = pf0.x; scol[ 1 * PA] = pf0.y; scol[ 2 * PA] = pf0.z; scol[ 3 * PA] = pf0.w;
        scol[ 4 * PA] = pf1.x; scol[ 5 * PA] = pf1.y; scol[ 6 * PA] = pf1.z; scol[ 7 * PA] = pf1.w;
        scol[ 8 * PA] = pf2.x; scol[ 9 * PA] = pf2.y; scol[10 * PA] = pf2.z; scol[11 * PA] = pf2.w;
        scol[12 * PA] = pf3.x; scol[13 * PA] = pf3.y; scol[14 * PA] = pf3.z; scol[15 * PA] = pf3.w;
        __syncthreads();

        if (c < 15) {
            const float* np = gp + (c + 1) * 16;
            pf0 = ((const float4*)np)[0];
            pf1 = ((const float4*)np)[1];
            pf2 = ((const float4*)np)[2];
            pf3 = ((const float4*)np)[3];
        }

#pragma unroll
        for (int k = 0; k < 16; k++) {
            float4 a0 = *(const float4*)&As[k * PA + 4 * tx];
            float4 a1 = *(const float4*)&As[k * PA + 64 + 4 * tx];
            float4 bv0 = *(const float4*)&Bs[k * PA + 4 * ty];
            float4 bv1 = *(const float4*)&Bs[k * PA + 64 + 4 * ty];
            u64 b00 = *(u64*)&bv0.x;
            u64 b01 = *(u64*)&bv0.z;
            u64 b10 = *(u64*)&bv1.x;
            u64 b11 = *(u64*)&bv1.z;

            u64 p;
            p = pack2(a0.x, a0.x);
            acc[0][0][0] = fma2(p, b00, acc[0][0][0]); acc[0][0][1] = fma2(p, b01, acc[0][0][1]);
            acc[0][0][2] = fma2(p, b10, acc[0][0][2]); acc[0][0][3] = fma2(p, b11, acc[0][0][3]);
            p = pack2(a0.y, a0.y);
            acc[0][1][0] = fma2(p, b00, acc[0][1][0]); acc[0][1][1] = fma2(p, b01, acc[0][1][1]);
            acc[0][1][2] = fma2(p, b10, acc[0][1][2]); acc[0][1][3] = fma2(p, b11, acc[0][1][3]);
            p = pack2(a0.z, a0.z);
            acc[0][2][0] = fma2(p, b00, acc[0][2][0]); acc[0][2][1] = fma2(p, b01, acc[0][2][1]);
            acc[0][2][2] = fma2(p, b10, acc[0][2][2]); acc[0][2][3] = fma2(p, b11, acc[0][2][3]);
            p = pack2(a0.w, a0.w);
            acc[0][3][0] = fma2(p, b00, acc[0][3][0]); acc[0][3][1] = fma2(p, b01, acc[0][3][1]);
            acc[0][3][2] = fma2(p, b10, acc[0][3][2]); acc[0][3][3] = fma2(p, b11, acc[0][3][3]);
            p = pack2(a1.x, a1.x);
            acc[1][0][0] = fma2(p, b00, acc[1][0][0]); acc[1][0][1] = fma2(p, b01, acc[1][0][1]);
            acc[1][0][2] = fma2(p, b10, acc[1][0][2]); acc[1][0][3] = fma2(p, b11, acc[1][0][3]);
            p = pack2(a1.y, a1.y);
            acc[1][1][0] = fma2(p, b00, acc[1][1][0]); acc[1][1][1] = fma2(p, b01, acc[1][1][1]);
            acc[1][1][2] = fma2(p, b10, acc[1][1][2]); acc[1][1][3] = fma2(p, b11, acc[1][1][3]);
            p = pack2(a1.z, a1.z);
            acc[1][2][0] = fma2(p, b00, acc[1][2][0]); acc[1][2][1] = fma2(p, b01, acc[1][2][1]);
            acc[1][2][2] = fma2(p, b10, acc[1][2][2]); acc[1][2][3] = fma2(p, b11, acc[1][2][3]);
            p = pack2(a1.w, a1.w);
            acc[1][3][0] = fma2(p, b00, acc[1][3][0]); acc[1][3][1] = fma2(p, b01, acc[1][3][1]);
            acc[1][3][2] = fma2(p, b10, acc[1][3][2]); acc[1][3][3] = fma2(p, b11, acc[1][3][3]);
        }
    }

    float4 biasA = *(const float4*)&g_bc[n0 + 4 * ty];
    float4 biasB = *(const float4*)&g_bc[n0 + 64 + 4 * ty];
#pragma unroll
    for (int tt = 0; tt < 2; tt++) {
#pragma unroll
        for (int i = 0; i < 4; i++) {
            int b = 4 * tx + i;
            float* op = g_gates + ((size_t)(t0 + tt) * B_ + b) * G4 + n0;
            float2 p0 = unpack2(acc[tt][i][0]);
            float2 p1 = unpack2(acc[tt][i][1]);
            float2 p2 = unpack2(acc[tt][i][2]);
            float2 p3 = unpack2(acc[tt][i][3]);
            *(float4*)&op[4 * ty] =
                make_float4(p0.x + biasA.x, p0.y + biasA.y, p1.x + biasA.z, p1.y + biasA.w);
            *(float4*)&op[64 + 4 * ty] =
                make_float4(p2.x + biasB.x, p2.y + biasB.y, p3.x + biasB.z, p3.y + biasB.w);
        }
    }
}

// ---------------- persistent scan kernel ----------------
// 128 blocks = 16 groups x 8 slices. Block (g,s): batches 4g..4g+3, units 32s..32s+31.
// W_hh slice in REGISTERS. h exchange: per-step sentinel-poisoned buffers — the
// consumer polls the DATA itself (ld.volatile.v4); when no word is the sentinel the
// loaded values are the payload. No flags, no fences, single L2 round trip per step.
__global__ __launch_bounds__(256, 1) void k_scan(const float* __restrict__ Whh,
                                                 float* __restrict__ out) {
    __shared__ float h_s2[NSL * 256];          // [ks][b][jl dup-pairs]  8KB
    __shared__ u64  psumU[32 * 65];            // [rq][(rp*8+ks)*4 + b]  pitch 65

    int tid = threadIdx.x;
    int bid = blockIdx.x;
    int g = bid >> 3, s = bid & 7;

    int ks = tid >> 5;            // warp id == peer slice polled
    int rq = tid & 31;            // row quad (rows 4rq..4rq+3)

    // ---- load W slice into registers, pre-packed as row-pairs ----
    u64 wA[32], wB[32];
    {
        int r0 = 4 * rq;
        int q = r0 >> 5;
        int jb = r0 & 31;
        const float* wb = Whh + (size_t)(q * 256 + s * 32 + jb) * 256 + 32 * ks;
#pragma unroll
        for (int kc = 0; kc < 32; kc++) {
            wA[kc] = pack2(wb[kc], wb[256 + kc]);
            wB[kc] = pack2(wb[512 + kc], wb[768 + kc]);
        }
    }

    // update identity (tid < 128)
    int ub = tid >> 5;            // 0..3 batch-local
    int jl = tid & 31;
    int bg = g * 4 + ub;          // global batch
    int jglob = s * 32 + jl;      // global hidden unit

    float c_reg = 0.f, c0_reg = 0.f;

    // ---- prologue t = 0 (h=0, c=0; carry c stays zero — faithful quirk) ----
    if (tid < 128) {
        const float* g0 = g_gates + (size_t)bg * G4;
        float zi = g0[0 * H_ + jglob];
        float zg = g0[2 * H_ + jglob];
        float zo = g0[3 * H_ + jglob];
        c0_reg = sigm(zi) * tanh_fast(zg);
        float h1 = sigm(zo) * tanh_fast(c0_reg);
        st_vol(g_hT + (((size_t)0 * NBG + g) * NSL + s) * 128 + jl * 4 + ub, h1);
        out[(size_t)bg * (T_ * H_) + jglob] = h1;
    }

    for (int t = 1; t < T_; t++) {
        // prefetch input gates + alpha (independent of poll, hides DRAM latency)
        float gin0 = 0.f, gin1 = 0.f, gin2 = 0.f, gin3 = 0.f, al = 0.f;
        if (tid < 128) {
            const float* gt = g_gates + ((size_t)t * B_ + bg) * G4;
            gin0 = gt[0 * H_ + jglob];
            gin1 = gt[1 * H_ + jglob];
            gin2 = gt[2 * H_ + jglob];
            gin3 = gt[3 * H_ + jglob];
            al   = g_alpha[((size_t)t * B_ + bg) * H_ + jglob];
        }

        // poll peer fragment: data IS the tag (sentinel = not yet written)
        {
            const float* fp = g_hT + (((size_t)(t - 1) * NBG + g) * NSL + ks) * 128 + rq * 4;
            uint4 u;
            do {
                u = ld_vol4(fp);
            } while (u.x == SENT || u.y == SENT || u.z == SENT || u.w == SENT);
            float2* d = (float2*)(h_s2 + ks * 256);
            float hx = __uint_as_float(u.x);
            float hy = __uint_as_float(u.y);
            float hz = __uint_as_float(u.z);
            float hw = __uint_as_float(u.w);
            d[0 * 32 + rq] = make_float2(hx, hx);
            d[1 * 32 + rq] = make_float2(hy, hy);
            d[2 * 32 + rq] = make_float2(hz, hz);
            d[3 * 32 + rq] = make_float2(hw, hw);
        }
        __syncwarp();

        // dot: W in regs, h via LDS.128 dup-pairs (2 kc per load), pure FFMA2
        {
            const float* hp = h_s2 + ks * 256;
            u64 a00 = 0, a01 = 0, a02 = 0, a03 = 0;
            u64 a10 = 0, a11 = 0, a12 = 0, a13 = 0;
#pragma unroll
            for (int m = 0; m < 16; m++) {
                float4 q0 = *(const float4*)(hp + 4 * m);
                float4 q1 = *(const float4*)(hp + 64 + 4 * m);
                float4 q2 = *(const float4*)(hp + 128 + 4 * m);
                float4 q3 = *(const float4*)(hp + 192 + 4 * m);
                u64 wa0 = wA[2 * m], wa1 = wA[2 * m + 1];
                u64 wb0 = wB[2 * m], wb1 = wB[2 * m + 1];
                u64 h00 = *(u64*)&q0.x, h01 = *(u64*)&q0.z;
                u64 h10 = *(u64*)&q1.x, h11 = *(u64*)&q1.z;
                u64 h20 = *(u64*)&q2.x, h21 = *(u64*)&q2.z;
                u64 h30 = *(u64*)&q3.x, h31 = *(u64*)&q3.z;
                a00 = fma2(wa0, h00, a00); a00 = fma2(wa1, h01, a00);
                a01 = fma2(wa0, h10, a01); a01 = fma2(wa1, h11, a01);
                a02 = fma2(wa0, h20, a02); a02 = fma2(wa1, h21, a02);
                a03 = fma2(wa0, h30, a03); a03 = fma2(wa1, h31, a03);
                a10 = fma2(wb0, h00, a10); a10 = fma2(wb1, h01, a10);
                a11 = fma2(wb0, h10, a11); a11 = fma2(wb1, h11, a11);
                a12 = fma2(wb0, h20, a12); a12 = fma2(wb1, h21, a12);
                a13 = fma2(wb0, h30, a13); a13 = fma2(wb1, h31, a13);
            }
            u64* pb = psumU + rq * 65 + ks * 4;
            pb[0] = a00; pb[1] = a01; pb[2] = a02; pb[3] = a03;
            pb[32 + 0] = a10; pb[32 + 1] = a11; pb[32 + 2] = a12; pb[32 + 3] = a13;
        }
        __syncthreads();   // psum ready

        // cell update: 128 threads, one per (batch, unit)
        if (tid < 128) {
            const float* pf = (const float*)psumU;
            int rqo = (jl >> 2);
            int off = ((jl >> 1) & 1) * 64 + ub * 2 + (jl & 1);
            float z[4] = {gin0, gin1, gin2, gin3};
#pragma unroll
            for (int q = 0; q < 4; q++) {
                const float* row = pf + (size_t)(q * 8 + rqo) * 130 + off;
                float sum = 0.f;
#pragma unroll
                for (int k8 = 0; k8 < 8; k8++) sum += row[k8 * 8];
                z[q] += sum;
            }
            float c = al * c0_reg + (1.f - al) * c_reg;
            c = sigm(z[1]) * c + sigm(z[0]) * tanh_fast(z[2]);
            c_reg = c;
            float h = sigm(z[3]) * tanh_fast(c);
            if (t < T_ - 1)
                st_vol(g_hT + (((size_t)t * NBG + g) * NSL + s) * 128 + jl * 4 + ub, h);
            out[(size_t)bg * (T_ * H_) + (size_t)t * H_ + jglob] = h;
        }
        __syncthreads();   // protect psumU / h_s2 reuse next iteration
    }
}

// ---------------- launch ----------------
extern "C" void kernel_launch(void* const* d_in, const int* in_sizes, int n_in,
                              void* d_out, int out_size) {
    (void)in_sizes; (void)n_in; (void)out_size;
    const float* values = (const float*)d_in[0];
    const float* Deltas = (const float*)d_in[1];
    const float* W_att  = (const float*)d_in[2];
    const float* b_att  = (const float*)d_in[3];
    const float* W_ih   = (const float*)d_in[4];
    const float* W_hh   = (const float*)d_in[5];
    const float* b_ih   = (const float*)d_in[6];
    const float* b_hh   = (const float*)d_in[7];
    float* out = (float*)d_out;

    // poison the per-step h buffers (sentinel tags) — must precede k_scan
    k_poison<<<(T_ * NBG * NSL * 128 / 4) / 256, 256>>>();
    k_wc<<<G4, D_>>>(W_ih, W_att);
    k_bc<<<G4 / 256, 256>>>(W_ih, b_att, b_ih, b_hh);
    k_vlin0<<<B_, D_>>>(values, W_att, b_att);
    k_gemm<<<dim3(T_ / 2, G4 / 128), 256>>>(values);
    k_a<<<(B_ * T_ * 32) / 256, 256>>>(values);
    k_alpha<<<B_, D_>>>(Deltas);
    k_scan<<<NB_SCAN, 256>>>(W_hh, out);
}